// round 11
// baseline (speedup 1.0000x reference)
#include <cuda_runtime.h>
#include <math.h>

// Problem constants (fixed by the dataset)
#define NN 64
#define PP 17
#define HH 192
#define WW 192
#define NP (NN * PP)            // 1088 items == 136 blocks * 8 warps

// ln(2) folded into stencil coefficients (per-lane log2):
#define C_HALF_LN2    0.34657359f
#define C_QUARTER_LN2 0.17328680f

__global__ __launch_bounds__(256)
void taylor_kernel(const float2* __restrict__ coords,
                   const float*  __restrict__ hm,
                   float2*       __restrict__ out)
{
    const int lane = threadIdx.x & 31;
    const int warp = threadIdx.x >> 5;
    const int i    = blockIdx.x * 8 + warp;      // exact fit: 136*8 = 1088

    // all lanes read the same coord (broadcast, 1 line)
    float2 c = coords[i];
    float xf = c.x * (float)WW;
    float yf = c.y * (float)HH;

    int px = (int)xf;                            // trunc == floor (coords >= 0)
    int py = (int)yf;

    bool inb = (px > 1) && (px < WW - 2) && (py > 1) && (py < HH - 2);

    int pxc = min(max(px, 2), WW - 3);
    int pyc = min(max(py, 2), HH - 3);

    // lane t < 25 -> stencil tap (dy = t/5 - 2, dx = t%5 - 2); lanes 25-31
    // duplicate tap 0. ONE LDG per warp covers the whole 5x5 stencil.
    int t  = (lane < 25) ? lane : 0;
    int dy = t / 5 - 2;
    int dx = t % 5 - 2;

    // 32-bit offset: max = 1087*36864 + 189*192 + 191 < 2^26, no 64-bit IMADs
    // on the coords->gather dependent chain.
    unsigned off = (unsigned)i * (HH * WW) + (unsigned)(pyc + dy) * WW
                 + (unsigned)(pxc + dx);
    float v = __ldg(hm + off);
    v = (v == 0.0f) ? 1e-10f : v;                // reference's zero substitution

    // Per-lane log BEFORE broadcast: one MUFU.LG2, parallel across lanes.
    float L = __log2f(v);

    // Broadcast the 13 needed log-taps. Tap index = (dy+2)*5 + (dx+2).
    const unsigned m = 0xFFFFFFFFu;
    float L00  = __shfl_sync(m, L, 12);          // ( 0, 0)
    float Lxp  = __shfl_sync(m, L, 13);          // ( 0, 1)
    float Lxm  = __shfl_sync(m, L, 11);          // ( 0,-1)
    float Lyp  = __shfl_sync(m, L, 17);          // ( 1, 0)
    float Lym  = __shfl_sync(m, L,  7);          // (-1, 0)
    float Lx2p = __shfl_sync(m, L, 14);          // ( 0, 2)
    float Lx2m = __shfl_sync(m, L, 10);          // ( 0,-2)
    float Ly2p = __shfl_sync(m, L, 22);          // ( 2, 0)
    float Ly2m = __shfl_sync(m, L,  2);          // (-2, 0)
    float Lpp  = __shfl_sync(m, L, 18);          // ( 1, 1)
    float Lmp  = __shfl_sync(m, L,  8);          // (-1, 1)
    float Lpm  = __shfl_sync(m, L, 16);          // ( 1,-1)
    float Lmm  = __shfl_sync(m, L,  6);          // (-1,-1)

    // Derivatives: linear combinations of log taps (reference math exactly,
    // up to log2 ULPs). FMA-form where it shortens the chain.
    float gdx = C_HALF_LN2    * (Lxp - Lxm);
    float gdy = C_HALF_LN2    * (Lyp - Lym);
    float dxx = C_QUARTER_LN2 * (Lx2p - 2.0f * L00 + Lx2m);
    float dxy = C_QUARTER_LN2 * (Lpp - Lmp - Lpm + Lmm);
    float dyy = C_QUARTER_LN2 * (Ly2p - 2.0f * L00 + Ly2m);

    float det = fmaf(dxx, dyy, -dxy * dxy);
    bool ok = inb && (det != 0.0f);

    if (ok) {
        float inv = __fdividef(1.0f, det);
        xf -= fmaf(dyy, gdx, -dxy * gdy) * inv;
        yf -= fmaf(dxx, gdy, -dxy * gdx) * inv;
    }

    if (lane == 0) {
        float2 o;
        o.x = yf * (1.0f / (float)HH);           // flip=True -> (y, x)
        o.y = xf * (1.0f / (float)WW);
        out[i] = o;
    }
}

extern "C" void kernel_launch(void* const* d_in, const int* in_sizes, int n_in,
                              void* d_out, int out_size)
{
    const float2* coords = (const float2*)d_in[0];
    const float*  hm     = (const float*)d_in[1];
    float2* out          = (float2*)d_out;

    (void)in_sizes; (void)n_in; (void)out_size;

    taylor_kernel<<<NP / 8, 256>>>(coords, hm, out);
}

// round 12
// speedup vs baseline: 1.0435x; 1.0435x over previous
#include <cuda_runtime.h>
#include <math.h>

// Problem constants (fixed by the dataset)
#define NN 64
#define PP 17
#define HH 192
#define WW 192
#define NP (NN * PP)            // 1088 items == 34 blocks * 32 threads exactly

// ln(2) folded into stencil coefficients (log2-domain math):
#define C_HALF_LN2    0.34657359f
#define C_QUARTER_LN2 0.17328680f

__global__ __launch_bounds__(32)
void taylor_kernel(const float2* __restrict__ coords,
                   const float*  __restrict__ hm,
                   float2*       __restrict__ out)
{
    // thread-per-item, exact fit: 34 * 32 == 1088, no bounds check.
    // One warp per block -> spread across 34 SMs, minimizing per-SM
    // L1tex wavefront queueing from the divergent 13-tap gather.
    int i = blockIdx.x * 32 + threadIdx.x;

    float2 c = coords[i];                        // (cx, cy) normalized
    float xf = c.x * (float)WW;
    float yf = c.y * (float)HH;

    int px = (int)xf;                            // trunc == floor (coords >= 0)
    int py = (int)yf;

    bool inb = (px > 1) && (px < WW - 2) && (py > 1) && (py < HH - 2);

    int pxc = min(max(px, 2), WW - 3);
    int pyc = min(max(py, 2), HH - 3);

    // 32-bit base offset: max index < 2^26, keeps the coords->gather chain
    // free of 64-bit IMAD pairs.
    unsigned base = (unsigned)i * (HH * WW) + (unsigned)pyc * WW + (unsigned)pxc;

    // 13 independent gathers, issued back-to-back (MLP ~13).
    auto ld = [&](int dy, int dx) -> float {
        float v = __ldg(hm + base + dy * WW + dx);
        return (v == 0.0f) ? 1e-10f : v;         // reference's zero substitution
    };

    float v00  = ld( 0,  0);
    float vxp  = ld( 0,  1);
    float vxm  = ld( 0, -1);
    float vyp  = ld( 1,  0);
    float vym  = ld(-1,  0);
    float vx2p = ld( 0,  2);
    float vx2m = ld( 0, -2);
    float vy2p = ld( 2,  0);
    float vy2m = ld(-2,  0);
    float vpp  = ld( 1,  1);
    float vmp  = ld(-1,  1);
    float vpm  = ld( 1, -1);
    float vmm  = ld(-1, -1);

    // Folded logs: 5 MUFU.LG2 instead of 13 logs. Operands bounded by
    // [1e-20, 1e20] (values in (0,1] with 1e-10 substitution) — safe in f32
    // and for __fdividef.
    float inv00sq = __fdividef(1.0f, v00 * v00);
    float gdx = C_HALF_LN2    * __log2f(__fdividef(vxp, vxm));
    float gdy = C_HALF_LN2    * __log2f(__fdividef(vyp, vym));
    float dxx = C_QUARTER_LN2 * __log2f(vx2p * vx2m * inv00sq);
    float dxy = C_QUARTER_LN2 * __log2f(__fdividef(vpp * vmm, vmp * vpm));
    float dyy = C_QUARTER_LN2 * __log2f(vy2p * vy2m * inv00sq);

    float det = fmaf(dxx, dyy, -dxy * dxy);
    bool ok = inb && (det != 0.0f);

    if (ok) {
        float inv = __fdividef(1.0f, det);
        xf -= fmaf(dyy, gdx, -dxy * gdy) * inv;
        yf -= fmaf(dxx, gdy, -dxy * gdx) * inv;
    }

    float2 o;
    o.x = yf * (1.0f / (float)HH);               // flip=True -> (y, x)
    o.y = xf * (1.0f / (float)WW);
    out[i] = o;
}

extern "C" void kernel_launch(void* const* d_in, const int* in_sizes, int n_in,
                              void* d_out, int out_size)
{
    const float2* coords = (const float2*)d_in[0];
    const float*  hm     = (const float*)d_in[1];
    float2* out          = (float2*)d_out;

    (void)in_sizes; (void)n_in; (void)out_size;

    taylor_kernel<<<NP / 32, 32>>>(coords, hm, out);
}